// round 1
// baseline (speedup 1.0000x reference)
#include <cuda_runtime.h>
#include <math.h>

#define W_IMG 128
#define NB 16

// ---------------- scratch (static device globals; no allocation) ----------------
__device__ float g_conv[41943040];   // conv output per stage (all stages: 41,943,040 elems)
__device__ float g_pool[20971520];   // pooled output / next-stage input
__device__ float g_maskA[524288];    // stage input mask (N,1,H,W)
__device__ float g_maskB[524288];    // full-res mask_next before pooling
__device__ float g_stats[1280];      // [sum(0..C), sumsq(C..2C)]
__device__ float g_feat[NB * 640];
__device__ float g_z1[NB * 256];
__device__ float g_z2[NB * 128];

// ---------------- prep: split data / clipped mask ----------------
__global__ void prep_kernel(const float* __restrict__ x) {
    int idx = blockIdx.x * blockDim.x + threadIdx.x;
    const int per = 256 * 128;
    if (idx >= NB * per) return;
    int n = idx / per;
    int rest = idx - n * per;
    g_pool[idx] = x[(n * 2 + 0) * per + rest];
    float m = x[(n * 2 + 1) * per + rest];
    g_maskA[idx] = fminf(fmaxf(m, 0.f), 1.f);
}

__global__ void zero_stats_kernel(int n) {
    int i = blockIdx.x * blockDim.x + threadIdx.x;
    if (i < n) g_stats[i] = 0.f;
}

// ---------------- partial conv 3x3 (fused scale/bias/zero + stats) ----------------
// block: (h = blockIdx.x, co tile = blockIdx.y*64, n = blockIdx.z)
// 256 threads: 32 pixel-groups (4 contiguous px each) x 8 co-groups (8 co each)
__launch_bounds__(256)
__global__ void pconv_kernel(const float* __restrict__ wts,
                             const float* __restrict__ bias,
                             int Cin, int Cout, int H)
{
    __shared__ __align__(16) float s_in[8][3][132];
    __shared__ __align__(16) float s_m[3][132];
    __shared__ __align__(16) float s_w[8][9][64];

    const int t    = threadIdx.x;
    const int h    = blockIdx.x;
    const int co0  = blockIdx.y * 64;
    const int n    = blockIdx.z;
    const int pxg  = t & 31;
    const int cog  = t >> 5;       // == warp id
    const int px0  = pxg * 4;
    const int lane = t & 31;

    // ---- mask tile with OOB = 1.0 (mask conv pads with ones) ----
    for (int idx = t; idx < 3 * 130; idx += 256) {
        int r = idx / 130, col = idx % 130;
        int hh = h - 1 + r, ww = col - 1;
        float v = 1.0f;
        if (hh >= 0 && hh < H && ww >= 0 && ww < W_IMG)
            v = g_maskA[(n * H + hh) * W_IMG + ww];
        s_m[r][col] = v;
    }
    __syncthreads();

    float msum[4];
    #pragma unroll
    for (int p = 0; p < 4; p++) {
        float s = 0.f;
        #pragma unroll
        for (int r = 0; r < 3; r++)
            #pragma unroll
            for (int tw = 0; tw < 3; tw++)
                s += s_m[r][px0 + p + tw];
        msum[p] = s;
    }

    float acc[8][4];
    #pragma unroll
    for (int j = 0; j < 8; j++)
        #pragma unroll
        for (int p = 0; p < 4; p++) acc[j][p] = 0.f;

    for (int ci0 = 0; ci0 < Cin; ci0 += 8) {
        __syncthreads();
        // input tile: (x * mask), OOB = 0
        for (int idx = t; idx < 8 * 3 * 130; idx += 256) {
            int c = idx / 390, rem = idx - c * 390;
            int r = rem / 130, col = rem - r * 130;
            int hh = h - 1 + r, ww = col - 1;
            int ci = ci0 + c;
            float v = 0.f;
            if (ci < Cin && hh >= 0 && hh < H && ww >= 0 && ww < W_IMG)
                v = g_pool[((n * Cin + ci) * H + hh) * W_IMG + ww] * s_m[r][col];
            s_in[c][r][col] = v;
        }
        // weight tile
        for (int idx = t; idx < 8 * 9 * 64; idx += 256) {
            int c = idx / 576, rem = idx - c * 576;
            int tap = rem / 64, co = rem - tap * 64;
            int gco = co0 + co, ci = ci0 + c;
            float v = 0.f;
            if (gco < Cout && ci < Cin)
                v = wts[(gco * Cin + ci) * 9 + tap];
            s_w[c][tap][co] = v;
        }
        __syncthreads();

        #pragma unroll
        for (int c = 0; c < 8; c++) {
            #pragma unroll
            for (int r = 0; r < 3; r++) {
                float iv[6];
                #pragma unroll
                for (int k = 0; k < 6; k++) iv[k] = s_in[c][r][px0 + k];
                #pragma unroll
                for (int tw = 0; tw < 3; tw++) {
                    float4 wA = *(const float4*)&s_w[c][r * 3 + tw][cog * 8];
                    float4 wB = *(const float4*)&s_w[c][r * 3 + tw][cog * 8 + 4];
                    float wj[8] = {wA.x, wA.y, wA.z, wA.w, wB.x, wB.y, wB.z, wB.w};
                    #pragma unroll
                    for (int j = 0; j < 8; j++)
                        #pragma unroll
                        for (int p = 0; p < 4; p++)
                            acc[j][p] += wj[j] * iv[tw + p];
                }
            }
        }
    }

    // ---- epilogue: scale, bias, zero-invalid, stats, mask_next ----
    float scale[4];
    bool  nov[4];
    #pragma unroll
    for (int p = 0; p < 4; p++) {
        float valid = (float)Cin * msum[p];
        nov[p]   = (valid <= 0.f);
        scale[p] = (float)(Cin * 9) / fmaxf(valid, 1.0f);
    }
    if (blockIdx.y == 0 && cog == 0) {
        #pragma unroll
        for (int p = 0; p < 4; p++)
            g_maskB[(n * H + h) * W_IMG + px0 + p] = nov[p] ? 0.f : 1.f;
    }

    #pragma unroll
    for (int j = 0; j < 8; j++) {
        int gco = co0 + cog * 8 + j;
        bool ok = (gco < Cout);
        float b = ok ? bias[gco] : 0.f;
        float ssum = 0.f, ssq = 0.f;
        #pragma unroll
        for (int p = 0; p < 4; p++) {
            float y = nov[p] ? 0.f : (acc[j][p] * scale[p] + b);
            if (ok) g_conv[((n * Cout + gco) * H + h) * W_IMG + px0 + p] = y;
            ssum += y;
            ssq  += y * y;
        }
        #pragma unroll
        for (int off = 16; off; off >>= 1) {
            ssum += __shfl_xor_sync(0xffffffffu, ssum, off);
            ssq  += __shfl_xor_sync(0xffffffffu, ssq,  off);
        }
        if (lane == 0 && ok) {
            atomicAdd(&g_stats[gco], ssum);
            atomicAdd(&g_stats[Cout + gco], ssq);
        }
    }
}

// ---------------- fused BN + ReLU + 2x1 max pool ----------------
__global__ void bn_pool_kernel(const float* __restrict__ gamma,
                               const float* __restrict__ beta,
                               int Cout, int Hc)
{
    int idx = blockIdx.x * blockDim.x + threadIdx.x;
    int Hp = Hc >> 1;
    int total = NB * Cout * Hp * W_IMG;
    if (idx >= total) return;
    int w  = idx % W_IMG;
    int hp = (idx / W_IMG) % Hp;
    int c  = (idx / (W_IMG * Hp)) % Cout;
    int n  = idx / (W_IMG * Hp * Cout);

    float cnt  = (float)(NB * Hc * W_IMG);
    float mean = g_stats[c] / cnt;
    float var  = g_stats[Cout + c] / cnt - mean * mean;
    float inv  = rsqrtf(var + 1e-5f);
    float ga = gamma[c], bb = beta[c];

    int base = ((n * Cout + c) * Hc + 2 * hp) * W_IMG + w;
    float v0 = g_conv[base];
    float v1 = g_conv[base + W_IMG];
    float r0 = fmaxf((v0 - mean) * inv * ga + bb, 0.f);
    float r1 = fmaxf((v1 - mean) * inv * ga + bb, 0.f);
    g_pool[((n * Cout + c) * Hp + hp) * W_IMG + w] = fmaxf(r0, r1);
}

__global__ void mask_pool_kernel(int Hc) {
    int idx = blockIdx.x * blockDim.x + threadIdx.x;
    int Hp = Hc >> 1;
    int total = NB * Hp * W_IMG;
    if (idx >= total) return;
    int w  = idx % W_IMG;
    int hp = (idx / W_IMG) % Hp;
    int n  = idx / (W_IMG * Hp);
    int base = (n * Hc + 2 * hp) * W_IMG + w;
    g_maskA[(n * Hp + hp) * W_IMG + w] = fmaxf(g_maskB[base], g_maskB[base + W_IMG]);
}

// ---------------- head ----------------
__global__ void feat_kernel() {
    __shared__ float sred[128];
    int nc = blockIdx.x;                 // n*640 + c
    const float* p = g_pool + (size_t)nc * 2048;  // 16*128
    float s = 0.f;
    for (int i = threadIdx.x; i < 2048; i += 128) s += p[i];
    sred[threadIdx.x] = s;
    __syncthreads();
    for (int o = 64; o; o >>= 1) {
        if (threadIdx.x < o) sred[threadIdx.x] += sred[threadIdx.x + o];
        __syncthreads();
    }
    if (threadIdx.x == 0) g_feat[nc] = sred[0] * (1.f / 2048.f);
}

__global__ void fc_kernel(const float* __restrict__ Wm, const float* __restrict__ b,
                          const float* __restrict__ in, float* __restrict__ out,
                          int IN, int OUT, int act)   // act: 0=relu, 1=sigmoid
{
    __shared__ float s[640];
    int n = blockIdx.x;
    for (int i = threadIdx.x; i < IN; i += blockDim.x) s[i] = in[n * IN + i];
    __syncthreads();
    int o = threadIdx.x;
    if (o < OUT) {
        float a = b[o];
        const float* wr = Wm + o * IN;
        for (int k = 0; k < IN; k++) a += wr[k] * s[k];
        if (act == 0) a = fmaxf(a, 0.f);
        else          a = 1.f / (1.f + expf(-a));
        out[n * OUT + o] = a;
    }
}

// ---------------- launch ----------------
extern "C" void kernel_launch(void* const* d_in, const int* in_sizes, int n_in,
                              void* d_out, int out_size)
{
    const float* x = (const float*)d_in[0];
    const float* w[4]  = {(const float*)d_in[1],  (const float*)d_in[5],
                          (const float*)d_in[9],  (const float*)d_in[13]};
    const float* bi[4] = {(const float*)d_in[2],  (const float*)d_in[6],
                          (const float*)d_in[10], (const float*)d_in[14]};
    const float* ga[4] = {(const float*)d_in[3],  (const float*)d_in[7],
                          (const float*)d_in[11], (const float*)d_in[15]};
    const float* be[4] = {(const float*)d_in[4],  (const float*)d_in[8],
                          (const float*)d_in[12], (const float*)d_in[16]};
    const float* fw1 = (const float*)d_in[17];
    const float* fb1 = (const float*)d_in[18];
    const float* fw2 = (const float*)d_in[19];
    const float* fb2 = (const float*)d_in[20];
    const float* hw  = (const float*)d_in[21];
    const float* hb  = (const float*)d_in[22];

    float *feat, *z1, *z2;
    cudaGetSymbolAddress((void**)&feat, g_feat);
    cudaGetSymbolAddress((void**)&z1,   g_z1);
    cudaGetSymbolAddress((void**)&z2,   g_z2);

    prep_kernel<<<(NB * 256 * 128 + 255) / 256, 256>>>(x);

    int Cin = 1, H = 256;
    const int Couts[4] = {80, 160, 320, 640};
    for (int s = 0; s < 4; s++) {
        int Cout = Couts[s];
        zero_stats_kernel<<<(2 * Cout + 255) / 256, 256>>>(2 * Cout);
        dim3 grid(H, (Cout + 63) / 64, NB);
        pconv_kernel<<<grid, 256>>>(w[s], bi[s], Cin, Cout, H);
        int Hp = H / 2;
        int total = NB * Cout * Hp * W_IMG;
        bn_pool_kernel<<<(total + 255) / 256, 256>>>(ga[s], be[s], Cout, H);
        mask_pool_kernel<<<(NB * Hp * W_IMG + 255) / 256, 256>>>(H);
        Cin = Cout; H = Hp;
    }

    feat_kernel<<<NB * 640, 128>>>();
    fc_kernel<<<NB, 256>>>(fw1, fb1, feat, z1, 640, 256, 0);
    fc_kernel<<<NB, 256>>>(fw2, fb2, z1, z2, 256, 128, 0);
    fc_kernel<<<NB, 128>>>(hw, hb, z2, (float*)d_out, 128, 1, 1);
}